// round 16
// baseline (speedup 1.0000x reference)
#include <cuda_runtime.h>
#include <float.h>

#define Bv 64
#define Nv 1024
#define Dv 128
#define Kv 6
#define CHUNKS 8          // 128 rows per main block, grid = 8 x 64 = 512
#define RPB 128
#define THR 128
#define GW 12             // 12x12 cell grid
#define NC (GW * GW)      // 144 cells
#define CELLW (1.0f / 12.0f)

typedef unsigned long long ull;

__device__ float  g_ABC[Kv * Dv * 3];           // [k][d][{A,B,C}]
__device__ float  g_partial[Bv * CHUNKS * Dv];  // [b][chunk][d]
__device__ float4 g_pts[Bv * Nv];               // (x, y, deadline, orig) cell-sorted
__device__ float2 g_p0[Bv * Nv];                // (x0, y0) cell-sorted order
__device__ int    g_cs[Bv * (NC + 1)];          // cell start offsets
__device__ int    g_count;                      // completion counter

// ---- packed f32x2 helpers (per-half rn == scalar rounding) ----
__device__ __forceinline__ ull f2add(ull a, ull b) {
    ull r; asm("add.rn.f32x2 %0,%1,%2;" : "=l"(r) : "l"(a), "l"(b)); return r;
}
__device__ __forceinline__ ull f2mul(ull a, ull b) {
    ull r; asm("mul.rn.f32x2 %0,%1,%2;" : "=l"(r) : "l"(a), "l"(b)); return r;
}
__device__ __forceinline__ ull f2fma(ull a, ull b, ull c) {
    ull r; asm("fma.rn.f32x2 %0,%1,%2,%3;" : "=l"(r) : "l"(a), "l"(b), "l"(c)); return r;
}
__device__ __forceinline__ ull f2pack(float lo, float hi) {
    ull r; asm("mov.b64 %0,{%1,%2};" : "=l"(r) : "f"(lo), "f"(hi)); return r;
}
__device__ __forceinline__ void f2unpack(ull v, float& lo, float& hi) {
    asm("mov.b64 {%0,%1},%2;" : "=f"(lo), "=f"(hi) : "l"(v));
}

__device__ __forceinline__ int cell_of(float x, float y) {
    int cx = min((int)(x * 12.0f), GW - 1);
    int cy = min((int)(y * 12.0f), GW - 1);
    return cy * GW + cx;
}

// ---------------------------------------------------------------------------
// Setup: blocks 0..63  -> per-batch counting sort by 2-D cell (144 cells)
//        blocks 64..111 -> ABC weight fold (one warp per (k,d))
// ---------------------------------------------------------------------------
__global__ __launch_bounds__(512) void setup_kernel(
    const float* __restrict__ loc, const float* __restrict__ deadline,
    const float* __restrict__ W2d, const float* __restrict__ b2d,
    const float* __restrict__ Wnb)
{
    __shared__ int cnt[NC];
    __shared__ int cs[NC + 1];
    const int t = threadIdx.x;

    if (blockIdx.x >= Bv) {
        int wid  = (blockIdx.x - Bv) * 16 + (t >> 5);
        int k    = wid >> 7, d = wid & (Dv - 1);
        int lane = t & 31;
        const float4* w4 = (const float4*)(Wnb + (size_t)d * (Kv * Dv) + k * Dv);
        float4 v  = w4[lane];
        const float4* w2 = (const float4*)W2d;
        float4 p0 = w2[lane * 2], p1 = w2[lane * 2 + 1];
        float4 bb = ((const float4*)b2d)[lane];
        float A = fmaf(v.x, p0.x, fmaf(v.y, p0.z, fmaf(v.z, p1.x, v.w * p1.z)));
        float B = fmaf(v.x, p0.y, fmaf(v.y, p0.w, fmaf(v.z, p1.y, v.w * p1.w)));
        float C = fmaf(v.x, bb.x, fmaf(v.y, bb.y, fmaf(v.z, bb.z, v.w * bb.w)));
#pragma unroll
        for (int s = 16; s > 0; s >>= 1) {
            A += __shfl_xor_sync(0xffffffffu, A, s);
            B += __shfl_xor_sync(0xffffffffu, B, s);
            C += __shfl_xor_sync(0xffffffffu, C, s);
        }
        if (lane == 0) {
            int base = (k * Dv + d) * 3;
            g_ABC[base + 0] = A; g_ABC[base + 1] = B; g_ABC[base + 2] = C;
        }
        return;
    }

    const int b = blockIdx.x;
    const float2* lb = (const float2*)(loc + (size_t)b * Nv * 2);
    const float2* l0 = (const float2*)loc;

    if (t < NC) cnt[t] = 0;
    float2 pa = lb[t], pb = lb[t + 512];
    float2 qa = l0[t], qb = l0[t + 512];
    float dla = deadline[(size_t)b * Nv + t];
    float dlb = deadline[(size_t)b * Nv + t + 512];
    __syncthreads();
    int ca = cell_of(pa.x, pa.y);
    int cb = cell_of(pb.x, pb.y);
    atomicAdd(&cnt[ca], 1);
    atomicAdd(&cnt[cb], 1);
    __syncthreads();

    // warp-parallel exclusive scan over 144 counters (lane i owns 5 cells)
    if (t < 32) {
        int v0 = 0, v1 = 0, v2 = 0, v3 = 0, v4 = 0;
        int i0 = t * 5;
        if (i0 + 0 < NC) v0 = cnt[i0 + 0];
        if (i0 + 1 < NC) v1 = cnt[i0 + 1];
        if (i0 + 2 < NC) v2 = cnt[i0 + 2];
        if (i0 + 3 < NC) v3 = cnt[i0 + 3];
        if (i0 + 4 < NC) v4 = cnt[i0 + 4];
        int tot = v0 + v1 + v2 + v3 + v4;
        int run = tot;
#pragma unroll
        for (int o = 1; o < 32; o <<= 1) {
            int u = __shfl_up_sync(0xffffffffu, run, o);
            if (t >= o) run += u;
        }
        int off = run - tot;   // exclusive
        if (i0 + 0 <= NC) cs[i0 + 0] = off;
        if (i0 + 1 <= NC) cs[i0 + 1] = off + v0;
        if (i0 + 2 <= NC) cs[i0 + 2] = off + v0 + v1;
        if (i0 + 3 <= NC) cs[i0 + 3] = off + v0 + v1 + v2;
        if (i0 + 4 <= NC) cs[i0 + 4] = off + v0 + v1 + v2 + v3;
        if (t == 31) cs[NC] = off + tot;
    }
    __syncthreads();
    if (t < NC) cnt[t] = cs[t];            // scatter cursors
    if (t <= NC) g_cs[b * (NC + 1) + t] = cs[t];
    __syncthreads();

    int posA = atomicAdd(&cnt[ca], 1);
    g_pts[(size_t)b * Nv + posA] = make_float4(pa.x, pa.y, dla, __int_as_float(t));
    g_p0[(size_t)b * Nv + posA]  = qa;
    int posB = atomicAdd(&cnt[cb], 1);
    g_pts[(size_t)b * Nv + posB] = make_float4(pb.x, pb.y, dlb, __int_as_float(t + 512));
    g_p0[(size_t)b * Nv + posB]  = qb;
}

// ---------------------------------------------------------------------------
// Main: 128 threads = 128 cell-sorted rows. Each thread scans its 3x3 cell
// neighborhood via 4-wide guarded unroll (MLP=4), exact strict-< top-6;
// geometric margin test drives exact ring expansion (rare).
// ---------------------------------------------------------------------------
__global__ __launch_bounds__(THR) void main_kernel(
    const float* __restrict__ W3d, const float* __restrict__ b3d,
    const float* __restrict__ bnb,
    const float* __restrict__ depot, const float* __restrict__ Wdep,
    const float* __restrict__ bdep, float* __restrict__ h_out)
{
    __shared__ __align__(16) float2 sxyv[Nv];      // cell-sorted coords     8 KB
    __shared__ int    scs[NC + 1];                 // cell starts          0.6 KB
    __shared__ float4 srow[RPB];                   // (x,y,deadline,orig)    2 KB
    __shared__ __align__(16) float2 snb[RPB * Kv]; // neighbor b0 coords     6 KB
    __shared__ float4 sW3[Dv];                     // (w0,w1,w2, base)       2 KB
    __shared__ __align__(16) float2 sAB[Kv * Dv];  // (A_k[d], B_k[d])       6 KB
    __shared__ int    sLast;

    const int b = blockIdx.y, chunk = blockIdx.x, t = threadIdx.x;

    {
        const float4* gp = g_pts + (size_t)b * Nv;
#pragma unroll
        for (int i = 0; i < Nv / THR; i++) {
            float4 q = gp[i * THR + t];
            sxyv[i * THR + t] = make_float2(q.x, q.y);
        }
        srow[t] = gp[chunk * RPB + t];
        for (int i = t; i <= NC; i += THR) scs[i] = g_cs[b * (NC + 1) + i];
    }
    {
        float sumC = 0.f;
#pragma unroll
        for (int k = 0; k < Kv; k++) {
            int base = (k * Dv + t) * 3;
            sAB[k * Dv + t] = make_float2(g_ABC[base], g_ABC[base + 1]);
            sumC += g_ABC[base + 2];
        }
        sW3[t] = make_float4(W3d[t * 3 + 0], W3d[t * 3 + 1], W3d[t * 3 + 2],
                             b3d[t] + bnb[t] + sumC);
    }
    __syncthreads();

    // ---- phase 2: 3x3 cell scan (4-wide guarded) + exact ring expansion ----
    const float4 me = srow[t];
    const float mx = me.x, my = me.y;
    const int cx = min((int)(mx * 12.0f), GW - 1);
    const int cy = min((int)(my * 12.0f), GW - 1);
    const ull negm = f2pack(-mx, -my);

    float e0 = FLT_MAX, e1 = FLT_MAX, e2 = FLT_MAX,
          e3 = FLT_MAX, e4 = FLT_MAX, e5 = FLT_MAX;
    int   j0 = 0, j1 = 0, j2 = 0, j3 = 0, j4 = 0, j5 = 0;

#define INS6(dd, cj)  do {                                                   \
        bool c0 = dd < e0, c1 = dd < e1, c2 = dd < e2,                       \
             c3 = dd < e3, c4 = dd < e4, c5 = dd < e5;                       \
        float m0 = fmaxf(e0, dd), m1 = fmaxf(e1, dd), m2 = fmaxf(e2, dd),    \
              m3 = fmaxf(e3, dd), m4 = fmaxf(e4, dd);                        \
        int   w0 = c0 ? j0 : cj, w1 = c1 ? j1 : cj, w2 = c2 ? j2 : cj,       \
              w3 = c3 ? j3 : cj, w4 = c4 ? j4 : cj;                          \
        e5 = c5 ? m4 : e5;  j5 = c5 ? w4 : j5;                               \
        e4 = c4 ? m3 : e4;  j4 = c4 ? w3 : j4;                               \
        e3 = c3 ? m2 : e3;  j3 = c3 ? w2 : j3;                               \
        e2 = c2 ? m1 : e2;  j2 = c2 ? w1 : j2;                               \
        e1 = c1 ? m0 : e1;  j1 = c1 ? w0 : j1;                               \
        e0 = c0 ? dd : e0;  j0 = c0 ? cj : j0;                               \
    } while (0)

    // 4-wide guarded span scan: 4 independent LDS.64 per iteration (MLP=4);
    // out-of-span candidates get dd=FLT_MAX (insert is a provable no-op).
#define SPAN4(JS, JE)  for (int j = (JS); j < (JE); j += 4) {                \
        int  jj0_ = j,     jj1_ = j + 1, jj2_ = j + 2, jj3_ = j + 3;         \
        bool v1_ = jj1_ < (JE), v2_ = jj2_ < (JE), v3_ = jj3_ < (JE);        \
        int  jc1_ = v1_ ? jj1_ : (JS), jc2_ = v2_ ? jj2_ : (JS),             \
             jc3_ = v3_ ? jj3_ : (JS);                                       \
        ull u0_ = *(const ull*)&sxyv[jj0_];                                  \
        ull u1_ = *(const ull*)&sxyv[jc1_];                                  \
        ull u2_ = *(const ull*)&sxyv[jc2_];                                  \
        ull u3_ = *(const ull*)&sxyv[jc3_];                                  \
        ull f0_ = f2add(u0_, negm), f1_ = f2add(u1_, negm),                  \
            f2_ = f2add(u2_, negm), f3_ = f2add(u3_, negm);                  \
        ull q0_ = f2mul(f0_, f0_), q1_ = f2mul(f1_, f1_),                    \
            q2_ = f2mul(f2_, f2_), q3_ = f2mul(f3_, f3_);                    \
        float a0_, b0_, a1_, b1_, a2_, b2_, a3_, b3_;                        \
        f2unpack(q0_, a0_, b0_); f2unpack(q1_, a1_, b1_);                    \
        f2unpack(q2_, a2_, b2_); f2unpack(q3_, a3_, b3_);                    \
        float d0_ = __fadd_rn(a0_, b0_);                                     \
        float d1_ = v1_ ? __fadd_rn(a1_, b1_) : FLT_MAX;                     \
        float d2_ = v2_ ? __fadd_rn(a2_, b2_) : FLT_MAX;                     \
        float d3_ = v3_ ? __fadd_rn(a3_, b3_) : FLT_MAX;                     \
        INS6(d0_, jj0_); INS6(d1_, jc1_);                                    \
        INS6(d2_, jc2_); INS6(d3_, jc3_);                                    \
    }

#define SPAN(JS, JE)  for (int j = (JS); j < (JE); j++) {                    \
        ull cvu  = *(const ull*)&sxyv[j];                                    \
        ull diff = f2add(cvu, negm);                                         \
        ull sq   = f2mul(diff, diff);                                        \
        float qlo, qhi; f2unpack(sq, qlo, qhi);                              \
        float dd = __fadd_rn(qlo, qhi);                                      \
        INS6(dd, j);                                                         \
    }

    {   // 3x3 neighborhood: three contiguous spans, 4-wide pipelined
        int xlo = max(cx - 1, 0), xhi = min(cx + 1, GW - 1);
#pragma unroll
        for (int dy = -1; dy <= 1; dy++) {
            int yy = cy + dy;
            if ((unsigned)yy < GW) {
                int js = scs[yy * GW + xlo];
                int je = scs[yy * GW + xhi + 1];
                SPAN4(js, je);
            }
        }
    }

    {   // exact ring expansion (rare): widen until margin^2 >= e5
        int R = 1;
        float ml = (cx - R >= 0)      ? mx - (float)(cx - R) * CELLW : 1e30f;
        float mr = (cx + R <= GW - 1) ? (float)(cx + R + 1) * CELLW - mx : 1e30f;
        float mb = (cy - R >= 0)      ? my - (float)(cy - R) * CELLW : 1e30f;
        float mt = (cy + R <= GW - 1) ? (float)(cy + R + 1) * CELLW - my : 1e30f;
        float mg = fmaxf(fminf(fminf(ml, mr), fminf(mb, mt)) - 1e-6f, 0.f);
        bool need = e5 > mg * mg;
        while (__any_sync(0xffffffffu, need) && R < GW) {
            R++;
            if (need) {
                int xlo = max(cx - R, 0), xhi = min(cx + R, GW - 1);
                int ytop = cy - R, ybot = cy + R;
                if (ytop >= 0)     { SPAN(scs[ytop * GW + xlo], scs[ytop * GW + xhi + 1]); }
                if (ybot <= GW - 1){ SPAN(scs[ybot * GW + xlo], scs[ybot * GW + xhi + 1]); }
                int yy0 = max(cy - R + 1, 0), yy1 = min(cy + R - 1, GW - 1);
                for (int yy = yy0; yy <= yy1; yy++) {
                    if (cx - R >= 0)     { SPAN(scs[yy * GW + cx - R], scs[yy * GW + cx - R + 1]); }
                    if (cx + R <= GW - 1){ SPAN(scs[yy * GW + cx + R], scs[yy * GW + cx + R + 1]); }
                }
                ml = (cx - R >= 0)      ? mx - (float)(cx - R) * CELLW : 1e30f;
                mr = (cx + R <= GW - 1) ? (float)(cx + R + 1) * CELLW - mx : 1e30f;
                mb = (cy - R >= 0)      ? my - (float)(cy - R) * CELLW : 1e30f;
                mt = (cy + R <= GW - 1) ? (float)(cy + R + 1) * CELLW - my : 1e30f;
                mg = fmaxf(fminf(fminf(ml, mr), fminf(mb, mt)) - 1e-6f, 0.f);
                need = e5 > mg * mg;
            }
        }
    }
#undef SPAN4
#undef SPAN
#undef INS6

    {   // neighbor batch-0 coords straight from L2 (6 parallel LDG.64)
        const float2* g0 = g_p0 + (size_t)b * Nv;
        snb[t*Kv+0] = g0[j0]; snb[t*Kv+1] = g0[j1]; snb[t*Kv+2] = g0[j2];
        snb[t*Kv+3] = g0[j3]; snb[t*Kv+4] = g0[j4]; snb[t*Kv+5] = g0[j5];
    }
    __syncthreads();

    // ---- phase 3: thread t = dim d; two independent row-chains per iter ----
    const int d = t;
    const float4 wv = sW3[d];
    const ull w01 = f2pack(wv.x, wv.y);
    ull AB[Kv];
#pragma unroll
    for (int k = 0; k < Kv; k++) AB[k] = *(const ull*)&sAB[k * Dv + d];

    float acc = 0.f;
#pragma unroll 2
    for (int r = 0; r < RPB; r += 2) {
        float4 rdA = srow[r], rdB = srow[r + 1];
        const ulonglong2* nA = (const ulonglong2*)(snb + r * Kv);
        const ulonglong2* nB = (const ulonglong2*)(snb + (r + 1) * Kv);
        ulonglong2 a0 = nA[0], a1 = nA[1], a2 = nA[2];
        ulonglong2 b0 = nB[0], b1 = nB[1], b2 = nB[2];
        ull sA = f2pack(wv.w, __fmul_rn(rdA.z, wv.z));
        ull sB = f2pack(wv.w, __fmul_rn(rdB.z, wv.z));
        sA = f2fma(f2pack(rdA.x, rdA.y), w01, sA);
        sB = f2fma(f2pack(rdB.x, rdB.y), w01, sB);
        sA = f2fma(a0.x, AB[0], sA);  sB = f2fma(b0.x, AB[0], sB);
        sA = f2fma(a0.y, AB[1], sA);  sB = f2fma(b0.y, AB[1], sB);
        sA = f2fma(a1.x, AB[2], sA);  sB = f2fma(b1.x, AB[2], sB);
        sA = f2fma(a1.y, AB[3], sA);  sB = f2fma(b1.y, AB[3], sB);
        sA = f2fma(a2.x, AB[4], sA);  sB = f2fma(b2.x, AB[4], sB);
        sA = f2fma(a2.y, AB[5], sA);  sB = f2fma(b2.y, AB[5], sB);
        float loA, hiA, loB, hiB;
        f2unpack(sA, loA, hiA); f2unpack(sB, loB, hiB);
        float vA = __fadd_rn(loA, hiA);
        float vB = __fadd_rn(loB, hiB);
        vA = fmaxf(vA, 0.01f * vA);              // leaky_relu(0.01)
        vB = fmaxf(vB, 0.01f * vB);
        h_out[((size_t)b * 1025 + 1 + __float_as_int(rdA.w)) * Dv + d] = vA;
        h_out[((size_t)b * 1025 + 1 + __float_as_int(rdB.w)) * Dv + d] = vB;
        acc += vA; acc += vB;
    }
    g_partial[((size_t)b * CHUNKS + chunk) * Dv + d] = acc;

    // ---- fused tail: last finishing block computes depot row + means ----
    __threadfence();
    if (t == 0) sLast = (atomicAdd(&g_count, 1) == CHUNKS * Bv - 1) ? 1 : 0;
    __syncthreads();
    if (sLast) {
        float w0 = Wdep[t * 2 + 0], w1 = Wdep[t * 2 + 1], bd = bdep[t];
        for (int bb = 0; bb < Bv; bb++) {
            float v = bd;
            v = fmaf(depot[bb * 2 + 0], w0, v);
            v = fmaf(depot[bb * 2 + 1], w1, v);
            v = fmaxf(v, 0.01f * v);
            h_out[(size_t)bb * 1025 * Dv + t] = v;       // h[bb, 0, d]
            float s = v;
#pragma unroll
            for (int c = 0; c < CHUNKS; c++)
                s += g_partial[((size_t)bb * CHUNKS + c) * Dv + t];
            h_out[(size_t)Bv * 1025 * Dv + bb * Dv + t] = s / 1025.0f;
        }
        if (t == 0) g_count = 0;                 // reset for next graph replay
    }
}

// ---------------------------------------------------------------------------
extern "C" void kernel_launch(void* const* d_in, const int* in_sizes, int n_in,
                              void* d_out, int out_size)
{
    const float* loc      = (const float*)d_in[0];
    const float* deadline = (const float*)d_in[1];
    const float* depot    = (const float*)d_in[2];
    const float* W3d      = (const float*)d_in[3];
    const float* b3d      = (const float*)d_in[4];
    const float* W2d      = (const float*)d_in[5];
    const float* b2d      = (const float*)d_in[6];
    const float* Wnb      = (const float*)d_in[7];
    const float* bnb      = (const float*)d_in[8];
    const float* Wdep     = (const float*)d_in[9];
    const float* bdep     = (const float*)d_in[10];
    float* out = (float*)d_out;

    setup_kernel<<<Bv + 48, 512>>>(loc, deadline, W2d, b2d, Wnb);
    dim3 grid(CHUNKS, Bv);
    main_kernel<<<grid, THR>>>(W3d, b3d, bnb, depot, Wdep, bdep, out);
}